// round 17
// baseline (speedup 1.0000x reference)
#include <cuda_runtime.h>
#include <cuda_bf16.h>
#include <math.h>
#include <stdint.h>

#define NMAX 50000
#define EMAX 800000
#define GMAX 100
#define FDIM 256

// ---------------- scratch (device globals) ---------------------------------
__device__ float g_h[NMAX * FDIM];
__device__ float g_xl[NMAX * FDIM];
__device__ float g_xr[NMAX * FDIM];
__device__ int   g_deg[NMAX];
__device__ int   g_cur[NMAX];
__device__ int   g_rowptr[NMAX + 1];
__device__ int   g_gstart[GMAX];
__device__ int   g_gend[GMAX];
__device__ int2  g_epair[EMAX];          // (src, ea bits) packed

// ---------------- helpers -----------------------------------------------------
typedef unsigned long long ull;
__device__ __forceinline__ float ex2f(float x) {
    float y;
    asm("ex2.approx.ftz.f32 %0, %1;" : "=f"(y) : "f"(x));
    return y;
}
__device__ __forceinline__ uint32_t tf32r(float x) {
    uint32_t y;
    asm("cvt.rna.tf32.f32 %0, %1;" : "=r"(y) : "f"(x));
    return y;
}

// ---------------- launch 0: encoder + hist + graph boundaries ------------------
__global__ void enc_hist_kernel(const float* __restrict__ x,
                                const float* __restrict__ W,
                                const float* __restrict__ b,
                                const int* __restrict__ dst,
                                const int* __restrict__ batch,
                                int N, int E) {
    int idx = blockIdx.x * blockDim.x + threadIdx.x;
    if (idx < N) {
        g_cur[idx] = 0;
        int bb = batch[idx];
        if (idx == 0 || batch[idx - 1] != bb) g_gstart[bb] = idx;
        if (idx == N - 1 || batch[idx + 1] != bb) g_gend[bb] = idx + 1;
    }
    if (idx < E) atomicAdd(&g_deg[dst[idx]], 1);
    if (idx < N * 64) {
        int n = idx >> 6, j = idx & 63;
        const float* xrow = x + n * 8;
        float acc = b[j];
#pragma unroll
        for (int k = 0; k < 8; ++k) acc = fmaf(xrow[k], W[k * 64 + j], acc);
        g_h[n * 64 + j] = fmaxf(acc, 0.f);
    }
}

// ---------------- launch 1: single-block scan (re-zeros g_deg) ----------------
__global__ __launch_bounds__(1024) void csr_scan(int N) {
    __shared__ int s[1024];
    const int tid = threadIdx.x;
    const int PER = (N + 1023) / 1024;
    const int base = tid * PER;
    int run = 0;
    for (int k = 0; k < PER; ++k) {
        int i = base + k;
        if (i < N) run += g_deg[i];
    }
    s[tid] = run;
    __syncthreads();
    for (int off = 1; off < 1024; off <<= 1) {
        int t = (tid >= off) ? s[tid - off] : 0;
        __syncthreads();
        s[tid] += t;
        __syncthreads();
    }
    int pre = s[tid] - run;
    if (tid == 0) g_rowptr[0] = 0;
    run = pre;
    for (int k = 0; k < PER; ++k) {
        int i = base + k;
        if (i < N) { run += g_deg[i]; g_rowptr[i + 1] = run; g_deg[i] = 0; }
    }
}

// ---------------- tf32 HMMA projection body (templated on K) -------------------
template <int K>
__device__ __forceinline__ void gemm_tf32_body(
    int blk, const float* __restrict__ Wl, const float* __restrict__ bl,
    const float* __restrict__ Wr, const float* __restrict__ br, int N,
    char* sm) {
    constexpr int SAF = K + 4;
    uint32_t* A_s = reinterpret_cast<uint32_t*>(sm);
    uint32_t* B_s = reinterpret_cast<uint32_t*>(sm + 128 * SAF * 4);

    const int tid = threadIdx.x;
    const int wid = tid >> 5, lane = tid & 31;
    const int g = lane >> 2, t = lane & 3;
    const int n0 = blk * 128;

    for (int idx = tid * 4; idx < 128 * K; idx += 256 * 4) {
        int r = idx / K, k = idx % K;
        uint4 val = make_uint4(0u, 0u, 0u, 0u);
        if (n0 + r < N) {
            float4 h4 = *reinterpret_cast<const float4*>(&g_h[(size_t)(n0 + r) * K + k]);
            val.x = tf32r(h4.x); val.y = tf32r(h4.y);
            val.z = tf32r(h4.z); val.w = tf32r(h4.w);
        }
        *reinterpret_cast<uint4*>(&A_s[r * SAF + k]) = val;
    }
    __syncthreads();

    const int rm = wid * 16;

    for (int c = 0; c < 8; ++c) {
        const float* W    = (c < 4) ? Wl : Wr;
        const float* bsv  = (c < 4) ? bl : br;
        float*       outp = (c < 4) ? g_xl : g_xr;
        const int nch = (c & 3) * 64;

        for (int it = tid; it < K * 16; it += 256) {
            int k = it >> 4;
            int n = (it & 15) * 4;
            float4 w4 = *reinterpret_cast<const float4*>(&W[(size_t)k * 256 + nch + n]);
            B_s[(n + 0) * SAF + k] = tf32r(w4.x);
            B_s[(n + 1) * SAF + k] = tf32r(w4.y);
            B_s[(n + 2) * SAF + k] = tf32r(w4.z);
            B_s[(n + 3) * SAF + k] = tf32r(w4.w);
        }
        __syncthreads();

        float acc[8][4];
#pragma unroll
        for (int nf = 0; nf < 8; ++nf)
#pragma unroll
            for (int q = 0; q < 4; ++q) acc[nf][q] = 0.f;

#pragma unroll 4
        for (int ks = 0; ks < K / 8; ++ks) {
            int k = ks * 8;
            const uint32_t* Ap = &A_s[(rm + g) * SAF + k + t];
            uint32_t a0 = Ap[0];
            uint32_t a1 = Ap[8 * SAF];
            uint32_t a2 = Ap[4];
            uint32_t a3 = Ap[8 * SAF + 4];
#pragma unroll
            for (int nf = 0; nf < 8; ++nf) {
                const uint32_t* Bp = &B_s[(nf * 8 + g) * SAF + k + t];
                uint32_t b0 = Bp[0];
                uint32_t b1 = Bp[4];
                asm volatile(
                    "mma.sync.aligned.m16n8k8.row.col.f32.tf32.tf32.f32 "
                    "{%0,%1,%2,%3}, {%4,%5,%6,%7}, {%8,%9}, {%0,%1,%2,%3};"
                    : "+f"(acc[nf][0]), "+f"(acc[nf][1]),
                      "+f"(acc[nf][2]), "+f"(acc[nf][3])
                    : "r"(a0), "r"(a1), "r"(a2), "r"(a3), "r"(b0), "r"(b1));
            }
        }

        int r0 = n0 + rm + g, r1 = r0 + 8;
#pragma unroll
        for (int nf = 0; nf < 8; ++nf) {
            int col = nch + nf * 8 + t * 2;
            float2 bv = *reinterpret_cast<const float2*>(&bsv[col]);
            if (r0 < N) {
                float2 o = make_float2(acc[nf][0] + bv.x, acc[nf][1] + bv.y);
                *reinterpret_cast<float2*>(&outp[(size_t)r0 * 256 + col]) = o;
            }
            if (r1 < N) {
                float2 o = make_float2(acc[nf][2] + bv.x, acc[nf][3] + bv.y);
                *reinterpret_cast<float2*>(&outp[(size_t)r1 * 256 + col]) = o;
            }
        }
        __syncthreads();
    }
}

#define TF32_SMEM_K64  (192 * 68 * 4)     // 52224
#define TF32_SMEM_K256 (192 * 260 * 4)    // 199680

// ---------------- launch 2: scatter + gemm1(tf32) role-split -------------------
__global__ __launch_bounds__(256) void scatter_gemm1(
    const int* __restrict__ src, const int* __restrict__ dst,
    const float* __restrict__ ea,
    const float* __restrict__ Wl, const float* __restrict__ bl,
    const float* __restrict__ Wr, const float* __restrict__ br,
    int N, int E, int ngemm) {
    extern __shared__ char sm[];
    if ((int)blockIdx.x < ngemm) {
        gemm_tf32_body<64>(blockIdx.x, Wl, bl, Wr, br, N, sm);
    } else {
        int e = (blockIdx.x - ngemm) * 256 + threadIdx.x;
        if (e < E) {
            int d = dst[e];
            int pos = g_rowptr[d] + atomicAdd(&g_cur[d], 1);
            g_epair[pos] = make_int2(src[e], __float_as_int(ea[e]));
        }
    }
}

// ---------------- launch 4: gemm2 tf32 ------------------------------------------
__global__ __launch_bounds__(256) void gemm2_tf32(
    const float* __restrict__ Wl, const float* __restrict__ bl,
    const float* __restrict__ Wr, const float* __restrict__ br, int N) {
    extern __shared__ char sm[];
    gemm_tf32_body<256>(blockIdx.x, Wl, bl, Wr, br, N, sm);
}

// ---------------- edge step: one edge's full chain (inlined) -------------------
__device__ __forceinline__ void edge_step(
    int s, float w, int lane,
    const float4& x0, const float4& x1,
    const float4& e0, const float4& e1,
    const float4& t0, const float4& t1,
    float4& acc0, float4& acc1, float& s0, float& s1) {
    const float4* xl4 = reinterpret_cast<const float4*>(g_xl + (size_t)s * 256);
    float4 a0 = xl4[lane];
    float4 a1 = xl4[lane + 32];

    float v, p0, p1;
    v = a0.x + x0.x + w * e0.x; v = (v > 0.f) ? v : 0.2f * v; p0 = v * t0.x;
    v = a0.y + x0.y + w * e0.y; v = (v > 0.f) ? v : 0.2f * v; p0 = fmaf(v, t0.y, p0);
    v = a0.z + x0.z + w * e0.z; v = (v > 0.f) ? v : 0.2f * v; p0 = fmaf(v, t0.z, p0);
    v = a0.w + x0.w + w * e0.w; v = (v > 0.f) ? v : 0.2f * v; p0 = fmaf(v, t0.w, p0);
    v = a1.x + x1.x + w * e1.x; v = (v > 0.f) ? v : 0.2f * v; p1 = v * t1.x;
    v = a1.y + x1.y + w * e1.y; v = (v > 0.f) ? v : 0.2f * v; p1 = fmaf(v, t1.y, p1);
    v = a1.z + x1.z + w * e1.z; v = (v > 0.f) ? v : 0.2f * v; p1 = fmaf(v, t1.z, p1);
    v = a1.w + x1.w + w * e1.w; v = (v > 0.f) ? v : 0.2f * v; p1 = fmaf(v, t1.w, p1);

#pragma unroll
    for (int off = 8; off; off >>= 1) {
        p0 += __shfl_xor_sync(0xffffffffu, p0, off);
        p1 += __shfl_xor_sync(0xffffffffu, p1, off);
    }

    float ew0 = ex2f(p0);
    float ew1 = ex2f(p1);
    s0 += ew0;
    s1 += ew1;
    acc0.x = fmaf(ew0, a0.x, acc0.x);
    acc0.y = fmaf(ew0, a0.y, acc0.y);
    acc0.z = fmaf(ew0, a0.z, acc0.z);
    acc0.w = fmaf(ew0, a0.w, acc0.w);
    acc1.x = fmaf(ew1, a1.x, acc1.x);
    acc1.y = fmaf(ew1, a1.y, acc1.y);
    acc1.z = fmaf(ew1, a1.z, acc1.z);
    acc1.w = fmaf(ew1, a1.w, acc1.w);
}

// ---------------- launches 3 & 5: PERSISTENT warp-per-dst GAT ------------------
// Fixed grid; each warp strides over dst nodes. We/att hoisted out of the loop.
__global__ __launch_bounds__(256, 4) void gat_fused(
    const float* __restrict__ We, const float* __restrict__ att,
    const float* __restrict__ bias, int N) {
    const int lane = threadIdx.x & 31;
    const int gw = blockIdx.x * 8 + (threadIdx.x >> 5);
    const int nw = gridDim.x * 8;

    const float4* We4p  = reinterpret_cast<const float4*>(We);
    const float4* att4p = reinterpret_cast<const float4*>(att);
    const float4* b4p   = reinterpret_cast<const float4*>(bias);

    const float LOG2E = 1.44269504088896f;
    const float4 e0 = We4p[lane], e1 = We4p[lane + 32];
    float4 t0 = att4p[lane], t1 = att4p[lane + 32];
    t0.x *= LOG2E; t0.y *= LOG2E; t0.z *= LOG2E; t0.w *= LOG2E;
    t1.x *= LOG2E; t1.y *= LOG2E; t1.z *= LOG2E; t1.w *= LOG2E;
    const float4 bb0 = b4p[lane], bb1 = b4p[lane + 32];

    for (int d = gw; d < N; d += nw) {
        const int start = g_rowptr[d];
        const int deg = g_rowptr[d + 1] - start;
        float4* hout = reinterpret_cast<float4*>(g_h + (size_t)d * 256);

        if (deg > 0) {
            const float4* xr4p = reinterpret_cast<const float4*>(g_xr + (size_t)d * 256);
            const float4 x0 = xr4p[lane], x1 = xr4p[lane + 32];

            float4 acc0 = {0.f, 0.f, 0.f, 0.f}, acc1 = {0.f, 0.f, 0.f, 0.f};
            float s0 = 0.f, s1 = 0.f;

            for (int base = 0; base < deg; base += 32) {
                int cnt = deg - base; if (cnt > 32) cnt = 32;
                int2 myep = (lane < cnt) ? g_epair[start + base + lane]
                                         : make_int2(0, 0);
                int i = 0;
                for (; i + 2 <= cnt; i += 2) {
                    int   sA = __shfl_sync(0xffffffffu, myep.x, i);
                    float wA = __int_as_float(__shfl_sync(0xffffffffu, myep.y, i));
                    int   sB = __shfl_sync(0xffffffffu, myep.x, i + 1);
                    float wB = __int_as_float(__shfl_sync(0xffffffffu, myep.y, i + 1));
                    edge_step(sA, wA, lane, x0, x1, e0, e1, t0, t1, acc0, acc1, s0, s1);
                    edge_step(sB, wB, lane, x0, x1, e0, e1, t0, t1, acc0, acc1, s0, s1);
                }
                if (i < cnt) {
                    int   sA = __shfl_sync(0xffffffffu, myep.x, i);
                    float wA = __int_as_float(__shfl_sync(0xffffffffu, myep.y, i));
                    edge_step(sA, wA, lane, x0, x1, e0, e1, t0, t1, acc0, acc1, s0, s1);
                }
            }

            float inv0 = 1.f / (s0 + 1e-16f);
            float inv1 = 1.f / (s1 + 1e-16f);
            float4 o0, o1;
            o0.x = fmaxf(fmaf(acc0.x, inv0, bb0.x), 0.f);
            o0.y = fmaxf(fmaf(acc0.y, inv0, bb0.y), 0.f);
            o0.z = fmaxf(fmaf(acc0.z, inv0, bb0.z), 0.f);
            o0.w = fmaxf(fmaf(acc0.w, inv0, bb0.w), 0.f);
            o1.x = fmaxf(fmaf(acc1.x, inv1, bb1.x), 0.f);
            o1.y = fmaxf(fmaf(acc1.y, inv1, bb1.y), 0.f);
            o1.z = fmaxf(fmaf(acc1.z, inv1, bb1.z), 0.f);
            o1.w = fmaxf(fmaf(acc1.w, inv1, bb1.w), 0.f);
            hout[lane] = o0;
            hout[lane + 32] = o1;
        } else {
            float4 o0, o1;
            o0.x = fmaxf(bb0.x, 0.f); o0.y = fmaxf(bb0.y, 0.f);
            o0.z = fmaxf(bb0.z, 0.f); o0.w = fmaxf(bb0.w, 0.f);
            o1.x = fmaxf(bb1.x, 0.f); o1.y = fmaxf(bb1.y, 0.f);
            o1.z = fmaxf(bb1.z, 0.f); o1.w = fmaxf(bb1.w, 0.f);
            hout[lane] = o0;
            hout[lane + 32] = o1;
        }
    }
}

// ---------------- launch 6: pooled head MLP (sorted-batch segment mean) --------
__global__ __launch_bounds__(128) void mlp_kernel(
    const float* __restrict__ p1W, const float* __restrict__ p1b,
    const float* __restrict__ lng, const float* __restrict__ lnb,
    const float* __restrict__ p2W, const float* __restrict__ p2b,
    float* __restrict__ out) {
    int g = blockIdx.x;
    __shared__ float ps[256];
    __shared__ float zs[128];
    __shared__ float red[128];
    int j = threadIdx.x;

    int lo = g_gstart[g], hi = g_gend[g];
    float inv = 1.f / fmaxf((float)(hi - lo), 1.f);
    float a0 = 0.f, a1 = 0.f;
#pragma unroll 4
    for (int n = lo; n < hi; ++n) {
        a0 += g_h[(size_t)n * 256 + j];
        a1 += g_h[(size_t)n * 256 + 128 + j];
    }
    ps[j] = a0 * inv;
    ps[j + 128] = a1 * inv;
    __syncthreads();
    if (j == 0) { g_gstart[g] = 0; g_gend[g] = 0; }

    float z = p1b[j];
    for (int k = 0; k < 256; ++k) z = fmaf(ps[k], p1W[k * 128 + j], z);

    red[j] = z;
    __syncthreads();
    for (int s = 64; s; s >>= 1) { if (j < s) red[j] += red[j + s]; __syncthreads(); }
    float mu = red[0] * (1.f / 128.f);
    __syncthreads();
    float dz = z - mu;
    red[j] = dz * dz;
    __syncthreads();
    for (int s = 64; s; s >>= 1) { if (j < s) red[j] += red[j + s]; __syncthreads(); }
    float var = red[0] * (1.f / 128.f);
    float zn = dz * rsqrtf(var + 1e-5f) * lng[j] + lnb[j];
    zs[j] = fmaxf(zn, 0.f);
    __syncthreads();

    if (j < 64) {
        float o = p2b[j];
        for (int k = 0; k < 128; ++k) o = fmaf(zs[k], p2W[k * 64 + j], o);
        out[g * 64 + j] = fmaxf(o, 0.f);
    }
}

// ---------------- driver ----------------------------------------------------------
extern "C" void kernel_launch(void* const* d_in, const int* in_sizes, int n_in,
                              void* d_out, int out_size) {
    const float* x      = (const float*)d_in[0];
    const int*   ei     = (const int*)  d_in[1];
    const float* ea     = (const float*)d_in[2];
    const int*   batch  = (const int*)  d_in[3];
    const float* enc_W  = (const float*)d_in[4];
    const float* enc_b  = (const float*)d_in[5];
    const float* g1_Wl  = (const float*)d_in[6];
    const float* g1_bl  = (const float*)d_in[7];
    const float* g1_Wr  = (const float*)d_in[8];
    const float* g1_br  = (const float*)d_in[9];
    const float* g1_We  = (const float*)d_in[10];
    const float* g1_att = (const float*)d_in[11];
    const float* g1_bias= (const float*)d_in[12];
    const float* g2_Wl  = (const float*)d_in[13];
    const float* g2_bl  = (const float*)d_in[14];
    const float* g2_Wr  = (const float*)d_in[15];
    const float* g2_br  = (const float*)d_in[16];
    const float* g2_We  = (const float*)d_in[17];
    const float* g2_att = (const float*)d_in[18];
    const float* g2_bias= (const float*)d_in[19];
    const float* p1_W   = (const float*)d_in[20];
    const float* p1_b   = (const float*)d_in[21];
    const float* ln_g   = (const float*)d_in[22];
    const float* ln_b   = (const float*)d_in[23];
    const float* p2_W   = (const float*)d_in[24];
    const float* p2_b   = (const float*)d_in[25];

    const int N = in_sizes[3];
    const int E = in_sizes[2];
    const int G = out_size / 64;
    const int* src = ei;
    const int* dst = ei + E;
    const int T = 256;
    const int GAT_GRID = 608;   // 4 CTAs/SM on 152 SMs, persistent

    cudaFuncSetAttribute(scatter_gemm1, cudaFuncAttributeMaxDynamicSharedMemorySize,
                         TF32_SMEM_K64);
    cudaFuncSetAttribute(gemm2_tf32, cudaFuncAttributeMaxDynamicSharedMemorySize,
                         TF32_SMEM_K256);

    // 0: encoder + degree hist + graph boundaries
    enc_hist_kernel<<<(N * 64 + T - 1) / T, T>>>(x, enc_W, enc_b, dst, batch, N, E);
    // 1: rowptr scan (re-zeros g_deg)
    csr_scan<<<1, 1024>>>(N);
    // 2: edge scatter + layer-1 projections on tf32 HMMA (role-split grid)
    {
        int ngemm = (N + 127) / 128;
        int nscat = (E + T - 1) / T;
        scatter_gemm1<<<ngemm + nscat, T, TF32_SMEM_K64>>>(
            src, dst, ea, g1_Wl, g1_bl, g1_Wr, g1_br, N, E, ngemm);
    }
    // 3: layer-1 fused GAT (persistent)
    gat_fused<<<GAT_GRID, 256>>>(g1_We, g1_att, g1_bias, N);
    // 4: layer-2 projections on tf32 HMMA
    gemm2_tf32<<<(N + 127) / 128, 256, TF32_SMEM_K256>>>(g2_Wl, g2_bl, g2_Wr, g2_br, N);
    // 5: layer-2 fused GAT (persistent) -> g_h
    gat_fused<<<GAT_GRID, 256>>>(g2_We, g2_att, g2_bias, N);
    // 6: pooled head MLP (segment mean over sorted batch ranges)
    mlp_kernel<<<G, 128>>>(p1_W, p1_b, ln_g, ln_b, p2_W, p2_b, (float*)d_out);
}